// round 1
// baseline (speedup 1.0000x reference)
#include <cuda_runtime.h>

// ---------------------------------------------------------------------------
// Fused BN -> ternary(sign) -> 3x3 conv -> bias -> ReLU
// B=16, C_in=C_out=32, H=W=256, stride 1, pad 1.
//
// Strategy: direct conv, compute-bound on fp32 FMA pipe. Use packed
// fma.rn.f32x2 (SASS FFMA2) with accumulators paired along C_out to double
// fp32 throughput. Quantized input tile (with halo, zero-padded) and
// re-laid-out weights live in shared memory; 2 CTAs/SM.
// ---------------------------------------------------------------------------

#define H_IMG 256
#define W_IMG 256
#define C_IN  32
#define C_OUT 32
#define BATCH 16

#define TH 16          // output tile height per block
#define TW 32          // output tile width per block
#define QR (TH + 2)    // 18 halo rows
#define QC (TW + 2)    // 34 halo cols (row stride)

#define QSZ (C_IN * QR * QC)       // 19584 floats
#define WSZ (C_IN * 9 * C_OUT)     // 9216 floats
#define SMEM_FLOATS (QSZ + WSZ + 64)

__device__ __forceinline__ unsigned long long pack2(float lo, float hi) {
    unsigned long long r;
    asm("mov.b64 %0, {%1, %2};" : "=l"(r) : "f"(lo), "f"(hi));
    return r;
}
__device__ __forceinline__ void unpack2(unsigned long long v, float& lo, float& hi) {
    asm("mov.b64 {%0, %1}, %2;" : "=f"(lo), "=f"(hi) : "l"(v));
}
// d = a * b + d  on packed f32x2 (SASS FFMA2)
__device__ __forceinline__ void fma2(unsigned long long& d,
                                     unsigned long long a,
                                     unsigned long long b) {
    asm("fma.rn.f32x2 %0, %1, %2, %0;" : "+l"(d) : "l"(a), "l"(b));
}

__global__ __launch_bounds__(256, 2)
void tbconv_kernel(const float* __restrict__ x,
                   const float* __restrict__ gamma,
                   const float* __restrict__ beta,
                   const float* __restrict__ mean,
                   const float* __restrict__ var,
                   const float* __restrict__ w,
                   const float* __restrict__ bias,
                   float* __restrict__ out)
{
    extern __shared__ float sm[];
    float* qs    = sm;                 // [C_IN][QR][QC] quantized tile (+halo)
    float* ws    = sm + QSZ;           // [ci][tap][co] weights
    float* s_inv = ws + WSZ;           // [32] BN scale
    float* s_sh  = s_inv + 32;         // [32] BN shift

    const int tid = threadIdx.x;
    const int bx  = blockIdx.x * TW;
    const int by  = blockIdx.y * TH;
    const int bb  = blockIdx.z;

    // BN per-channel constants
    if (tid < 32) {
        float inv = gamma[tid] / sqrtf(var[tid] + 1e-4f);
        s_inv[tid] = inv;
        s_sh[tid]  = beta[tid] - mean[tid] * inv;
    }
    // weight relayout: ws[(ci*9+tap)*32+co] = conv_w[co][ci][tap]
    for (int i = tid; i < WSZ; i += 256) {
        int co  = i & 31;
        int t   = i >> 5;
        int tap = t % 9;
        int ci  = t / 9;
        ws[i] = w[(co * C_IN + ci) * 9 + tap];
    }
    __syncthreads();  // s_inv/s_sh ready for the tile build

    // Build quantized input tile with zero-padded halo
    const float* xb = x + (size_t)bb * C_IN * H_IMG * W_IMG;
    for (int i = tid; i < QSZ; i += 256) {
        int lx = i % QC;
        int t  = i / QC;
        int ly = t % QR;
        int ci = t / QR;
        int gy = by + ly - 1;
        int gx = bx + lx - 1;
        float q = 0.0f;
        if ((unsigned)gy < (unsigned)H_IMG && (unsigned)gx < (unsigned)W_IMG) {
            float xh = xb[(ci * H_IMG + gy) * W_IMG + gx] * s_inv[ci] + s_sh[ci];
            // torch semantics with threshold 0: x<=0 -> -1, else +1
            q = (xh > 0.0f) ? 1.0f : -1.0f;
        }
        qs[i] = q;
    }
    __syncthreads();

    // Thread mapping: 4 x-chunks (8px) x 16 rows x 4 co-groups (8 co) = 256
    const int cx  = tid & 3;
    const int ty  = (tid >> 2) & 15;
    const int cog = tid >> 6;
    const int x0  = cx * 8;
    const int co0 = cog * 8;

    // Accumulators: 4 co-pairs x 8 pixels, packed f32x2 along C_out
    unsigned long long acc[4][8];
#pragma unroll
    for (int j = 0; j < 4; ++j)
#pragma unroll
        for (int p = 0; p < 8; ++p) acc[j][p] = 0ull;

    for (int ci = 0; ci < C_IN; ++ci) {
        const float* qbase = qs + (ci * QR + ty) * QC + x0;
        const float* wbase = ws + ci * 9 * 32 + co0;
#pragma unroll
        for (int dy = 0; dy < 3; ++dy) {
#pragma unroll
            for (int dx = 0; dx < 3; ++dx) {
                const float* qrow = qbase + dy * QC + dx;
                const float* wr   = wbase + (dy * 3 + dx) * 32;

                unsigned long long w2[4];
#pragma unroll
                for (int j = 0; j < 4; ++j)
                    w2[j] = *reinterpret_cast<const unsigned long long*>(wr + 2 * j);

                unsigned long long q2[8];
#pragma unroll
                for (int p = 0; p < 8; ++p) {
                    float qv = qrow[p];
                    q2[p] = pack2(qv, qv);
                }
#pragma unroll
                for (int p = 0; p < 8; ++p) {
#pragma unroll
                    for (int j = 0; j < 4; ++j)
                        fma2(acc[j][p], q2[p], w2[j]);
                }
            }
        }
    }

    // Epilogue: bias + ReLU + store
    const int oy = by + ty;
    float* ob = out + (size_t)bb * C_OUT * H_IMG * W_IMG;
#pragma unroll
    for (int j = 0; j < 4; ++j) {
        int c0 = co0 + 2 * j;
        float b0 = __ldg(bias + c0);
        float b1 = __ldg(bias + c0 + 1);
#pragma unroll
        for (int p = 0; p < 8; ++p) {
            float lo, hi;
            unpack2(acc[j][p], lo, hi);
            lo = fmaxf(lo + b0, 0.0f);
            hi = fmaxf(hi + b1, 0.0f);
            int ox = bx + x0 + p;
            ob[(c0 * H_IMG + oy) * W_IMG + ox]       = lo;
            ob[((c0 + 1) * H_IMG + oy) * W_IMG + ox] = hi;
        }
    }
}

extern "C" void kernel_launch(void* const* d_in, const int* in_sizes, int n_in,
                              void* d_out, int out_size)
{
    const float* x     = (const float*)d_in[0];
    const float* gamma = (const float*)d_in[1];
    const float* beta  = (const float*)d_in[2];
    const float* mean  = (const float*)d_in[3];
    const float* var   = (const float*)d_in[4];
    const float* w     = (const float*)d_in[5];
    const float* bias  = (const float*)d_in[6];
    float* out = (float*)d_out;

    size_t smem = SMEM_FLOATS * sizeof(float);
    cudaFuncSetAttribute(tbconv_kernel,
                         cudaFuncAttributeMaxDynamicSharedMemorySize, (int)smem);

    dim3 grid(W_IMG / TW, H_IMG / TH, BATCH);  // 8 x 16 x 16
    dim3 block(256);
    tbconv_kernel<<<grid, block, smem>>>(x, gamma, beta, mean, var, w, bias, out);
}

// round 2
// speedup vs baseline: 2.8279x; 2.8279x over previous
#include <cuda_runtime.h>
#include <cuda_fp16.h>

// ---------------------------------------------------------------------------
// Fused BN -> sign quantize (+-1) -> 3x3 conv -> bias -> ReLU
// as fp16 tensor-core implicit GEMM (mma.sync.m16n8k16, fp32 accum).
// B=16, C_in=C_out=32, H=W=256, stride 1, pad 1.
// CTA: 4 output rows x 128 px x 32 co. 8 warps, each 64px x 32co.
// K-loop: 9 taps x 2 k-steps of 16 ci.
// ---------------------------------------------------------------------------

#define H_IMG 256
#define W_IMG 256
#define HW    (H_IMG * W_IMG)
#define C_INC 32
#define BATCH 16

#define TH    4            // output rows per CTA
#define TPX   128          // output px per CTA
#define QROWS 6            // TH + 2 halo
#define QPX   132          // 130 used (128 + 2 halo), padded
#define CIP   40           // padded ci stride (fp16) -> 80B pixel stride
#define WCIP  40           // padded ci stride for weights

#define QSZ   (QROWS * QPX * CIP)   // 31680 fp16
#define WSZ   (9 * 32 * WCIP)       // 11520 fp16
#define NT    256

__device__ __forceinline__ void ldsm_x4(unsigned &a0, unsigned &a1,
                                        unsigned &a2, unsigned &a3,
                                        unsigned addr) {
    asm volatile("ldmatrix.sync.aligned.m8n8.x4.shared.b16 {%0,%1,%2,%3}, [%4];"
                 : "=r"(a0), "=r"(a1), "=r"(a2), "=r"(a3) : "r"(addr));
}
__device__ __forceinline__ void ldsm_x2(unsigned &b0, unsigned &b1, unsigned addr) {
    asm volatile("ldmatrix.sync.aligned.m8n8.x2.shared.b16 {%0,%1}, [%2];"
                 : "=r"(b0), "=r"(b1) : "r"(addr));
}
__device__ __forceinline__ void mma16816(float &c0, float &c1, float &c2, float &c3,
                                         unsigned a0, unsigned a1, unsigned a2, unsigned a3,
                                         unsigned b0, unsigned b1) {
    asm volatile("mma.sync.aligned.m16n8k16.row.col.f32.f16.f16.f32 "
                 "{%0,%1,%2,%3},{%4,%5,%6,%7},{%8,%9},{%0,%1,%2,%3};"
                 : "+f"(c0), "+f"(c1), "+f"(c2), "+f"(c3)
                 : "r"(a0), "r"(a1), "r"(a2), "r"(a3), "r"(b0), "r"(b1));
}

__global__ __launch_bounds__(NT, 2)
void tbconv_mma_kernel(const float* __restrict__ x,
                       const float* __restrict__ gamma,
                       const float* __restrict__ beta,
                       const float* __restrict__ mean,
                       const float* __restrict__ var,
                       const float* __restrict__ w,
                       const float* __restrict__ bias,
                       float* __restrict__ out)
{
    extern __shared__ char smraw[];
    __half* qh = (__half*)smraw;                   // [QROWS][QPX][CIP]
    __half* wh = qh + QSZ;                          // [tap][co][WCIP]
    float*  s_inv = (float*)(wh + WSZ);             // [32]
    float*  s_sh  = s_inv + 32;                     // [32]

    const int tid  = threadIdx.x;
    const int bx   = blockIdx.x * TPX;
    const int by   = blockIdx.y * TH;
    const int bb   = blockIdx.z;

    // ---- BN constants ----
    if (tid < 32) {
        float inv = gamma[tid] * rsqrtf(var[tid] + 1e-4f);
        s_inv[tid] = inv;
        s_sh[tid]  = beta[tid] - mean[tid] * inv;
    }
    // ---- weights -> fp16, layout [tap][co][ci] ----
    for (int i = tid; i < 32 * 32 * 9; i += NT) {
        int co  = i / 288;
        int rem = i % 288;
        int ci  = rem / 9;
        int tap = rem % 9;
        wh[(tap * 32 + co) * WCIP + ci] = __float2half(w[i]);
    }
    __syncthreads();

    // ---- build quantized tile: q[row][px][ci], 2 ci per thread-item ----
    const float* xb = x + (size_t)bb * C_INC * HW;
    for (int i = tid; i < QROWS * 16 * QPX; i += NT) {
        int p  = i % QPX;
        int t  = i / QPX;
        int cp = t % 16;          // ci pair
        int r  = t / 16;          // halo row 0..5
        int gy = by + r - 1;
        int gx = bx + p - 1;
        __half2 qv = __floats2half2_rn(0.0f, 0.0f);
        if (p < 130 && (unsigned)gy < (unsigned)H_IMG && (unsigned)gx < (unsigned)W_IMG) {
            int c0 = 2 * cp;
            float f0 = xb[(size_t)c0 * HW + gy * W_IMG + gx] * s_inv[c0] + s_sh[c0];
            float f1 = xb[(size_t)(c0 + 1) * HW + gy * W_IMG + gx] * s_inv[c0 + 1] + s_sh[c0 + 1];
            float q0 = (f0 > 0.0f) ? 1.0f : -1.0f;
            float q1 = (f1 > 0.0f) ? 1.0f : -1.0f;
            qv = __floats2half2_rn(q0, q1);
        }
        *(__half2*)&qh[(r * QPX + p) * CIP + 2 * cp] = qv;
    }
    __syncthreads();

    // ---- mainloop ----
    const int lane = tid & 31;
    const int wid  = tid >> 5;
    const int wr   = wid >> 1;          // warp out-row 0..3
    const int wx   = (wid & 1) * 64;    // warp x offset

    // A ldmatrix lane mapping: mat = lane>>3; mat0:(px,ci0) mat1:(px+8,ci0)
    // mat2:(px,ci+8) mat3:(px+8,ci+8)
    const int pxl0 = (lane & 7) + ((lane >> 3) & 1) * 8;
    const int cih  = (lane >> 4) * 8;
    // B ldmatrix (x2) lane mapping: lanes 0-7 -> co rows ci0; 8-15 -> ci+8
    const int laneB = lane & 15;
    const int b_row = laneB & 7;
    const int b_cih = (laneB >> 3) * 8;

    const unsigned qbase = (unsigned)__cvta_generic_to_shared(qh);
    const unsigned wbase = (unsigned)__cvta_generic_to_shared(wh);

    float acc[4][4][4];
#pragma unroll
    for (int mt = 0; mt < 4; ++mt)
#pragma unroll
        for (int nt = 0; nt < 4; ++nt)
#pragma unroll
            for (int k = 0; k < 4; ++k) acc[mt][nt][k] = 0.0f;

#pragma unroll
    for (int tap = 0; tap < 9; ++tap) {
        const int dy = tap / 3, dx = tap % 3;
        const unsigned abase = qbase +
            ((((wr + dy) * QPX) + wx + dx + pxl0) * CIP + cih) * 2u;
        const unsigned bbase = wbase +
            (((tap * 32 + b_row) * WCIP) + b_cih) * 2u;
#pragma unroll
        for (int s = 0; s < 2; ++s) {
            unsigned bf[4][2];
#pragma unroll
            for (int nt = 0; nt < 4; ++nt)
                ldsm_x2(bf[nt][0], bf[nt][1], bbase + (nt * 8 * WCIP + s * 16) * 2u);
#pragma unroll
            for (int mt = 0; mt < 4; ++mt) {
                unsigned a0, a1, a2, a3;
                ldsm_x4(a0, a1, a2, a3, abase + (mt * 16 * CIP + s * 16) * 2u);
#pragma unroll
                for (int nt = 0; nt < 4; ++nt)
                    mma16816(acc[mt][nt][0], acc[mt][nt][1], acc[mt][nt][2], acc[mt][nt][3],
                             a0, a1, a2, a3, bf[nt][0], bf[nt][1]);
            }
        }
    }

    // ---- epilogue: bias + ReLU + store ----
    float* ob = out + (size_t)bb * C_INC * HW;
    const int oy = by + wr;
    const int m0 = lane >> 2;
    const int cb = (lane & 3) * 2;
#pragma unroll
    for (int nt = 0; nt < 4; ++nt) {
        const int co = nt * 8 + cb;
        const float b0 = __ldg(bias + co);
        const float b1 = __ldg(bias + co + 1);
        float* o0 = ob + (size_t)co * HW + oy * W_IMG;
        float* o1 = ob + (size_t)(co + 1) * HW + oy * W_IMG;
#pragma unroll
        for (int mt = 0; mt < 4; ++mt) {
            const int px = bx + wx + mt * 16 + m0;
            o0[px]     = fmaxf(acc[mt][nt][0] + b0, 0.0f);
            o1[px]     = fmaxf(acc[mt][nt][1] + b1, 0.0f);
            o0[px + 8] = fmaxf(acc[mt][nt][2] + b0, 0.0f);
            o1[px + 8] = fmaxf(acc[mt][nt][3] + b1, 0.0f);
        }
    }
}

extern "C" void kernel_launch(void* const* d_in, const int* in_sizes, int n_in,
                              void* d_out, int out_size)
{
    const float* x     = (const float*)d_in[0];
    const float* gamma = (const float*)d_in[1];
    const float* beta  = (const float*)d_in[2];
    const float* mean  = (const float*)d_in[3];
    const float* var   = (const float*)d_in[4];
    const float* w     = (const float*)d_in[5];
    const float* bias  = (const float*)d_in[6];
    float* out = (float*)d_out;

    size_t smem = (QSZ + WSZ) * sizeof(__half) + 64 * sizeof(float) + 128;
    cudaFuncSetAttribute(tbconv_mma_kernel,
                         cudaFuncAttributeMaxDynamicSharedMemorySize, (int)smem);

    dim3 grid(W_IMG / TPX, H_IMG / TH, BATCH);  // 2 x 64 x 16 = 2048
    tbconv_mma_kernel<<<grid, NT, smem>>>(x, gamma, beta, mean, var, w, bias, out);
}

// round 3
// speedup vs baseline: 3.4060x; 1.2044x over previous
#include <cuda_runtime.h>
#include <cuda_fp16.h>

// ---------------------------------------------------------------------------
// Fused BN -> sign(+-1) -> 3x3 conv -> bias -> ReLU, fp16 tensor-core
// implicit GEMM, software-pipelined persistent CTAs, double-buffered smem.
// B=16, C=32, 256x256. Tile: 4 rows x 64 px x 32 co per CTA-iteration.
// ---------------------------------------------------------------------------

#define HW      65536
#define W_IMG   256
#define H_IMG   256
#define C_CH    32

#define TH      4
#define TPX     64
#define QROWS   6            // TH + 2 halo
#define QPXU    66           // used px incl halo
#define QPX     68           // padded px stride count
#define CIP     40           // ci stride (halfs) -> 80B px stride, ldsm-safe
#define WCIP    40

#define QTILE   (QROWS * QPX * CIP)   // 16320 halfs per buffer
#define WSZ     (9 * 32 * WCIP)       // 11520 halfs
#define NT      256
#define NCTA    296                   // 2 per SM x 148
#define NTILES  4096                  // 16 batch x 64 ytiles x 4 xtiles
#define NIT     (QROWS * QPXU * 16)   // 6336 build items (ci-pairs)

__device__ __forceinline__ void ldsm_x4(unsigned &a0, unsigned &a1,
                                        unsigned &a2, unsigned &a3,
                                        unsigned addr) {
    asm volatile("ldmatrix.sync.aligned.m8n8.x4.shared.b16 {%0,%1,%2,%3}, [%4];"
                 : "=r"(a0), "=r"(a1), "=r"(a2), "=r"(a3) : "r"(addr));
}
__device__ __forceinline__ void ldsm_x2(unsigned &b0, unsigned &b1, unsigned addr) {
    asm volatile("ldmatrix.sync.aligned.m8n8.x2.shared.b16 {%0,%1}, [%2];"
                 : "=r"(b0), "=r"(b1) : "r"(addr));
}
__device__ __forceinline__ void mma16816(float &c0, float &c1, float &c2, float &c3,
                                         unsigned a0, unsigned a1, unsigned a2, unsigned a3,
                                         unsigned b0, unsigned b1) {
    asm volatile("mma.sync.aligned.m16n8k16.row.col.f32.f16.f16.f32 "
                 "{%0,%1,%2,%3},{%4,%5,%6,%7},{%8,%9},{%0,%1,%2,%3};"
                 : "+f"(c0), "+f"(c1), "+f"(c2), "+f"(c3)
                 : "r"(a0), "r"(a1), "r"(a2), "r"(a3), "r"(b0), "r"(b1));
}

__device__ __forceinline__ void item_decode(int i, int &r, int &px, int &cp) {
    int t = i / QPXU;
    px = i - t * QPXU;
    cp = t / QROWS;
    r  = t - cp * QROWS;
}

__global__ __launch_bounds__(NT, 2)
void tbconv_pipe_kernel(const float* __restrict__ x,
                        const float* __restrict__ gamma,
                        const float* __restrict__ beta,
                        const float* __restrict__ mean,
                        const float* __restrict__ var,
                        const float* __restrict__ w,
                        const float* __restrict__ bias,
                        float* __restrict__ out)
{
    extern __shared__ char smraw[];
    __half* q0 = (__half*)smraw;            // buffer 0
    __half* q1 = q0 + QTILE;                // buffer 1
    __half* wh = q1 + QTILE;                // [tap][co][ci]
    float4* sinvsh = (float4*)(wh + WSZ);   // [16] (inv0, sh0, inv1, sh1)

    const int tid  = threadIdx.x;
    const int lane = tid & 31;
    const int wid  = tid >> 5;

    // ---- one-time CTA setup ----
    if (tid < 16) {
        int c0 = 2 * tid;
        float i0 = gamma[c0]     * rsqrtf(var[c0]     + 1e-4f);
        float i1 = gamma[c0 + 1] * rsqrtf(var[c0 + 1] + 1e-4f);
        sinvsh[tid] = make_float4(i0, beta[c0]     - mean[c0]     * i0,
                                  i1, beta[c0 + 1] - mean[c0 + 1] * i1);
    }
    for (int i = tid; i < 32 * 32 * 9; i += NT) {
        int co  = i / 288;
        int rem = i % 288;
        int ci  = rem / 9;
        int tap = rem % 9;
        wh[(tap * 32 + co) * WCIP + ci] = __float2half(w[i]);
    }

    // warp tiling: 8 warps -> (row 0..3) x (x-half 0/32); warp = 32px x 32co
    const int wr = wid >> 1;
    const int wx = (wid & 1) * 32;
    const int pxl0 = (lane & 7) + ((lane >> 3) & 1) * 8;
    const int cih  = (lane >> 4) * 8;
    const int laneB = lane & 15;
    const int b_row = laneB & 7;
    const int b_cih = (laneB >> 3) * 8;
    const int m0 = lane >> 2;
    const int cb = (lane & 3) * 2;

    float bias_lo[4], bias_hi[4];
#pragma unroll
    for (int nt = 0; nt < 4; ++nt) {
        bias_lo[nt] = __ldg(bias + nt * 8 + cb);
        bias_hi[nt] = __ldg(bias + nt * 8 + cb + 1);
    }

    const unsigned q0a = (unsigned)__cvta_generic_to_shared(q0);
    const unsigned q1a = (unsigned)__cvta_generic_to_shared(q1);
    const unsigned wba = (unsigned)__cvta_generic_to_shared(wh);

    float acc[2][4][4];
#pragma unroll
    for (int mt = 0; mt < 2; ++mt)
#pragma unroll
        for (int nt = 0; nt < 4; ++nt)
#pragma unroll
            for (int k = 0; k < 4; ++k) acc[mt][nt][k] = 0.0f;

    // ---- tile bookkeeping ----
    int tile = blockIdx.x;
    int b  = tile >> 8;
    int by = ((tile >> 2) & 63) << 2;
    int bx = (tile & 3) << 6;

    __syncthreads();  // sinvsh + weights ready

    // ---- prologue: direct build of first tile into q0 ----
    {
        const float* xb = x + (size_t)b * C_CH * HW;
#pragma unroll 1
        for (int k = 0; k < 25; ++k) {
            int i = tid + (k << 8);
            if (i >= NIT) break;
            int r, px, cp; item_decode(i, r, px, cp);
            int gy = by + r - 1, gx = bx + px - 1;
            bool ok = ((unsigned)gy < 256u) & ((unsigned)gx < 256u);
            float f0 = 0.f, f1 = 0.f;
            if (ok) {
                const float* p = xb + (size_t)(2 * cp) * HW + (gy << 8) + gx;
                f0 = __ldg(p); f1 = __ldg(p + HW);
            }
            float4 s = sinvsh[cp];
            float v0 = fmaf(f0, s.x, s.y), v1 = fmaf(f1, s.z, s.w);
            unsigned lo = ok ? (v0 > 0.f ? 0x3C00u : 0xBC00u) : 0u;
            unsigned hi = ok ? (v1 > 0.f ? 0x3C00u : 0xBC00u) : 0u;
            unsigned val = lo | (hi << 16);
            unsigned dst = q0a + (((r * QPX + px) * CIP + 2 * cp) << 1);
            asm volatile("st.shared.b32 [%0], %1;" :: "r"(dst), "r"(val));
        }
    }
    __syncthreads();

    bool flip = false;

    // ---- main pipelined loop ----
    while (true) {
        const unsigned qc = flip ? q1a : q0a;
        const unsigned qn = flip ? q0a : q1a;

        const int nxt = tile + NCTA;
        const bool hasnext = (nxt < NTILES);
        int nb = 0, nby = 0, nbx = 0;
        if (hasnext) {
            nb  = nxt >> 8;
            nby = ((nxt >> 2) & 63) << 2;
            nbx = (nxt & 3) << 6;
        }
        const float* xbn = x + (size_t)nb * C_CH * HW;

        float rawA[13][2], rawB[12][2];

        // stage-A loads (items 0..12) for next tile
        if (hasnext) {
#pragma unroll
            for (int k = 0; k < 13; ++k) {
                int i = tid + (k << 8);
                int r, px, cp; item_decode(i, r, px, cp);
                int gy = nby + r - 1, gx = nbx + px - 1;
                bool ok = ((unsigned)gy < 256u) & ((unsigned)gx < 256u);
                float f0 = 0.f, f1 = 0.f;
                if (ok) {
                    const float* p = xbn + (size_t)(2 * cp) * HW + (gy << 8) + gx;
                    f0 = __ldg(p); f1 = __ldg(p + HW);
                }
                rawA[k][0] = f0; rawA[k][1] = f1;
            }
        }

        // MMA stage s = 0 (hides stage-A load latency)
#pragma unroll
        for (int tap = 0; tap < 9; ++tap) {
            const int dy = tap / 3, dx = tap % 3;
            const unsigned abase = qc +
                ((((wr + dy) * QPX + wx + dx + pxl0) * CIP + cih) << 1);
            const unsigned bbase = wba +
                ((((tap * 32 + b_row) * WCIP) + b_cih) << 1);
            unsigned bf[4][2];
#pragma unroll
            for (int nt = 0; nt < 4; ++nt)
                ldsm_x2(bf[nt][0], bf[nt][1], bbase + ((nt * 8 * WCIP) << 1));
#pragma unroll
            for (int mt = 0; mt < 2; ++mt) {
                unsigned a0, a1, a2, a3;
                ldsm_x4(a0, a1, a2, a3, abase + ((mt * 16 * CIP) << 1));
#pragma unroll
                for (int nt = 0; nt < 4; ++nt)
                    mma16816(acc[mt][nt][0], acc[mt][nt][1], acc[mt][nt][2], acc[mt][nt][3],
                             a0, a1, a2, a3, bf[nt][0], bf[nt][1]);
            }
        }

        // convert + STS stage-A into next buffer
        if (hasnext) {
#pragma unroll
            for (int k = 0; k < 13; ++k) {
                int i = tid + (k << 8);
                int r, px, cp; item_decode(i, r, px, cp);
                int gy = nby + r - 1, gx = nbx + px - 1;
                bool ok = ((unsigned)gy < 256u) & ((unsigned)gx < 256u);
                float4 s = sinvsh[cp];
                float v0 = fmaf(rawA[k][0], s.x, s.y);
                float v1 = fmaf(rawA[k][1], s.z, s.w);
                unsigned lo = ok ? (v0 > 0.f ? 0x3C00u : 0xBC00u) : 0u;
                unsigned hi = ok ? (v1 > 0.f ? 0x3C00u : 0xBC00u) : 0u;
                unsigned val = lo | (hi << 16);
                unsigned dst = qn + (((r * QPX + px) * CIP + 2 * cp) << 1);
                asm volatile("st.shared.b32 [%0], %1;" :: "r"(dst), "r"(val));
            }
            // stage-B loads (items 13..24)
#pragma unroll
            for (int k = 13; k < 25; ++k) {
                int i = tid + (k << 8);
                int r, px, cp; item_decode(i, r, px, cp);
                int gy = nby + r - 1, gx = nbx + px - 1;
                bool ok = (i < NIT) & ((unsigned)gy < 256u) & ((unsigned)gx < 256u);
                float f0 = 0.f, f1 = 0.f;
                if (ok) {
                    const float* p = xbn + (size_t)(2 * cp) * HW + (gy << 8) + gx;
                    f0 = __ldg(p); f1 = __ldg(p + HW);
                }
                rawB[k - 13][0] = f0; rawB[k - 13][1] = f1;
            }
        }

        // MMA stage s = 1 (hides stage-B load latency)
#pragma unroll
        for (int tap = 0; tap < 9; ++tap) {
            const int dy = tap / 3, dx = tap % 3;
            const unsigned abase = qc +
                ((((wr + dy) * QPX + wx + dx + pxl0) * CIP + cih + 16) << 1);
            const unsigned bbase = wba +
                ((((tap * 32 + b_row) * WCIP) + b_cih + 16) << 1);
            unsigned bf[4][2];
#pragma unroll
            for (int nt = 0; nt < 4; ++nt)
                ldsm_x2(bf[nt][0], bf[nt][1], bbase + ((nt * 8 * WCIP) << 1));
#pragma unroll
            for (int mt = 0; mt < 2; ++mt) {
                unsigned a0, a1, a2, a3;
                ldsm_x4(a0, a1, a2, a3, abase + ((mt * 16 * CIP) << 1));
#pragma unroll
                for (int nt = 0; nt < 4; ++nt)
                    mma16816(acc[mt][nt][0], acc[mt][nt][1], acc[mt][nt][2], acc[mt][nt][3],
                             a0, a1, a2, a3, bf[nt][0], bf[nt][1]);
            }
        }

        // convert + STS stage-B
        if (hasnext) {
#pragma unroll
            for (int k = 13; k < 25; ++k) {
                int i = tid + (k << 8);
                int r, px, cp; item_decode(i, r, px, cp);
                int gy = nby + r - 1, gx = nbx + px - 1;
                bool ok = ((unsigned)gy < 256u) & ((unsigned)gx < 256u);
                float4 s = sinvsh[cp];
                float v0 = fmaf(rawB[k - 13][0], s.x, s.y);
                float v1 = fmaf(rawB[k - 13][1], s.z, s.w);
                unsigned lo = ok ? (v0 > 0.f ? 0x3C00u : 0xBC00u) : 0u;
                unsigned hi = ok ? (v1 > 0.f ? 0x3C00u : 0xBC00u) : 0u;
                unsigned val = lo | (hi << 16);
                if (i < NIT) {
                    unsigned dst = qn + (((r * QPX + px) * CIP + 2 * cp) << 1);
                    asm volatile("st.shared.b32 [%0], %1;" :: "r"(dst), "r"(val));
                }
            }
        }

        // ---- epilogue: bias + ReLU + store current tile ----
        {
            float* ob = out + (size_t)b * C_CH * HW;
            const int oy = by + wr;
#pragma unroll
            for (int nt = 0; nt < 4; ++nt) {
                const int co = nt * 8 + cb;
                float* o0 = ob + (size_t)co * HW + (oy << 8);
                float* o1 = o0 + HW;
#pragma unroll
                for (int mt = 0; mt < 2; ++mt) {
                    const int px = bx + wx + mt * 16 + m0;
                    o0[px]     = fmaxf(acc[mt][nt][0] + bias_lo[nt], 0.0f);
                    o1[px]     = fmaxf(acc[mt][nt][1] + bias_hi[nt], 0.0f);
                    o0[px + 8] = fmaxf(acc[mt][nt][2] + bias_lo[nt], 0.0f);
                    o1[px + 8] = fmaxf(acc[mt][nt][3] + bias_hi[nt], 0.0f);
                }
            }
        }
#pragma unroll
        for (int mt = 0; mt < 2; ++mt)
#pragma unroll
            for (int nt = 0; nt < 4; ++nt)
#pragma unroll
                for (int k = 0; k < 4; ++k) acc[mt][nt][k] = 0.0f;

        __syncthreads();
        if (!hasnext) break;
        tile = nxt; b = nb; by = nby; bx = nbx;
        flip = !flip;
    }
}

extern "C" void kernel_launch(void* const* d_in, const int* in_sizes, int n_in,
                              void* d_out, int out_size)
{
    const float* x     = (const float*)d_in[0];
    const float* gamma = (const float*)d_in[1];
    const float* beta  = (const float*)d_in[2];
    const float* mean  = (const float*)d_in[3];
    const float* var   = (const float*)d_in[4];
    const float* w     = (const float*)d_in[5];
    const float* bias  = (const float*)d_in[6];
    float* out = (float*)d_out;

    size_t smem = (size_t)(2 * QTILE + WSZ) * sizeof(__half) + 16 * sizeof(float4);
    cudaFuncSetAttribute(tbconv_pipe_kernel,
                         cudaFuncAttributeMaxDynamicSharedMemorySize, (int)smem);

    tbconv_pipe_kernel<<<NCTA, NT, smem>>>(x, gamma, beta, mean, var, w, bias, out);
}

// round 4
// speedup vs baseline: 4.3751x; 1.2845x over previous
#include <cuda_runtime.h>
#include <cuda_fp16.h>

// ---------------------------------------------------------------------------
// Fused BN -> sign(+-1) -> 3x3 conv -> bias -> ReLU, fp16 tensor-core
// implicit GEMM. Persistent CTAs, double-buffered smem pipeline,
// 3 CTAs/SM (24 warps) for latency hiding.
// Tile: 4 rows x 32 px x 32 co per CTA-iteration. 8 warps = 4 rows x 2 x-halves.
// ---------------------------------------------------------------------------

#define HW      65536
#define C_CH    32

#define TH      4
#define TPX     32
#define QROWS   6            // TH + 2 halo
#define QPX     34           // px incl halo
#define CIP     40           // ci stride (halfs) -> 80B px stride, ldsm-safe
#define WCIP    40

#define QTILE   (QROWS * QPX * CIP)   // 8160 halfs per buffer
#define WSZ     (9 * 32 * WCIP)       // 11520 halfs
#define NT      256
#define NCTA    444                   // 3 per SM x 148
#define NTILES  8192                  // 16 b x 64 ytiles x 8 xtiles

__device__ __forceinline__ void ldsm_x4(unsigned &a0, unsigned &a1,
                                        unsigned &a2, unsigned &a3,
                                        unsigned addr) {
    asm volatile("ldmatrix.sync.aligned.m8n8.x4.shared.b16 {%0,%1,%2,%3}, [%4];"
                 : "=r"(a0), "=r"(a1), "=r"(a2), "=r"(a3) : "r"(addr));
}
__device__ __forceinline__ void ldsm_x2(unsigned &b0, unsigned &b1, unsigned addr) {
    asm volatile("ldmatrix.sync.aligned.m8n8.x2.shared.b16 {%0,%1}, [%2];"
                 : "=r"(b0), "=r"(b1) : "r"(addr));
}
__device__ __forceinline__ void mma16816(float &c0, float &c1, float &c2, float &c3,
                                         unsigned a0, unsigned a1, unsigned a2, unsigned a3,
                                         unsigned b0, unsigned b1) {
    asm volatile("mma.sync.aligned.m16n8k16.row.col.f32.f16.f16.f32 "
                 "{%0,%1,%2,%3},{%4,%5,%6,%7},{%8,%9},{%0,%1,%2,%3};"
                 : "+f"(c0), "+f"(c1), "+f"(c2), "+f"(c3)
                 : "r"(a0), "r"(a1), "r"(a2), "r"(a3), "r"(b0), "r"(b1));
}

// quantize helper: packed half2 {-1,+1} or 0 when !ok
__device__ __forceinline__ unsigned quant2(float f0, float f1, float4 s, bool ok) {
    float v0 = fmaf(f0, s.x, s.y);
    float v1 = fmaf(f1, s.z, s.w);
    unsigned lo = ok ? (v0 > 0.f ? 0x3C00u : 0xBC00u) : 0u;
    unsigned hi = ok ? (v1 > 0.f ? 0x3C00u : 0xBC00u) : 0u;
    return lo | (hi << 16);
}
__device__ __forceinline__ void sts32(unsigned addr, unsigned val) {
    asm volatile("st.shared.b32 [%0], %1;" :: "r"(addr), "r"(val));
}

__global__ __launch_bounds__(NT, 3)
void tbconv_occ_kernel(const float* __restrict__ x,
                       const float* __restrict__ gamma,
                       const float* __restrict__ beta,
                       const float* __restrict__ mean,
                       const float* __restrict__ var,
                       const float* __restrict__ w,
                       const float* __restrict__ bias,
                       float* __restrict__ out)
{
    extern __shared__ char smraw[];
    __half* q0 = (__half*)smraw;            // buffer 0
    __half* q1 = q0 + QTILE;                // buffer 1
    __half* wh = q1 + QTILE;                // [tap][co][ci]
    float4* sinvsh = (float4*)(wh + WSZ);   // [16]
    float*  sbias  = (float*)(sinvsh + 16); // [32]

    const int tid  = threadIdx.x;
    const int lane = tid & 31;
    const int wid  = tid >> 5;

    // ---- one-time CTA setup ----
    if (tid < 16) {
        int c0 = 2 * tid;
        float i0 = gamma[c0]     * rsqrtf(var[c0]     + 1e-4f);
        float i1 = gamma[c0 + 1] * rsqrtf(var[c0 + 1] + 1e-4f);
        sinvsh[tid] = make_float4(i0, beta[c0]     - mean[c0]     * i0,
                                  i1, beta[c0 + 1] - mean[c0 + 1] * i1);
    }
    if (tid < 32) sbias[tid] = bias[tid];
    for (int i = tid; i < 32 * 32 * 9; i += NT) {
        int co  = i / 288;
        int rem = i % 288;
        int ci  = rem / 9;
        int tap = rem % 9;
        wh[(tap * 32 + co) * WCIP + ci] = __float2half(w[i]);
    }

    // warp tiling: wr = out row 0..3, wx = x-half 0/16; warp = 16px x 32co
    const int wr = wid >> 1;
    const int wx = (wid & 1) * 16;
    const int pxl0 = (lane & 7) + ((lane >> 3) & 1) * 8;
    const int cih  = (lane >> 4) * 8;
    const int laneB = lane & 15;
    const int b_row = laneB & 7;
    const int b_cih = (laneB >> 3) * 8;
    const int m0 = lane >> 2;
    const int cb = (lane & 3) * 2;

    const unsigned q0a = (unsigned)__cvta_generic_to_shared(q0);
    const unsigned q1a = (unsigned)__cvta_generic_to_shared(q1);
    const unsigned wba = (unsigned)__cvta_generic_to_shared(wh);

    // halo item for this thread (threads 0..191): px 0 or 33
    const int hidx  = tid >> 1;          // 0..95 (valid if tid<192)
    const int hside = tid & 1;
    const int hr    = hidx >> 4;         // 0..5
    const int hcp   = hidx & 15;
    const int hpx   = hside ? 33 : 0;

    float acc[4][4];
#pragma unroll
    for (int nt = 0; nt < 4; ++nt)
#pragma unroll
        for (int k = 0; k < 4; ++k) acc[nt][k] = 0.0f;

    int tile = blockIdx.x;
    int b  = tile >> 9;
    int by = ((tile >> 3) & 63) << 2;
    int bx = (tile & 7) << 5;

    __syncthreads();  // setup visible

    // ---- prologue: build first tile into q0 ----
    {
        const float* xb = x + (size_t)b * C_CH * HW;
#pragma unroll
        for (int k = 0; k < 12; ++k) {
            int row = wid + (k << 3);        // 0..95
            int r   = row >> 4;
            int cp  = row & 15;
            int gy  = by + r - 1;
            bool ok = (unsigned)gy < 256u;
            float f0 = 0.f, f1 = 0.f;
            if (ok) {
                const float* p = xb + (size_t)(2 * cp) * HW + (gy << 8) + bx + lane;
                f0 = __ldg(p); f1 = __ldg(p + HW);
            }
            sts32(q0a + (((r * QPX + lane + 1) * CIP + 2 * cp) << 1),
                  quant2(f0, f1, sinvsh[cp], ok));
        }
        if (tid < 192) {
            int gy = by + hr - 1;
            int gx = bx + hpx - 1;
            bool ok = ((unsigned)gy < 256u) & ((unsigned)gx < 256u);
            float f0 = 0.f, f1 = 0.f;
            if (ok) {
                const float* p = xb + (size_t)(2 * hcp) * HW + (gy << 8) + gx;
                f0 = __ldg(p); f1 = __ldg(p + HW);
            }
            sts32(q0a + (((hr * QPX + hpx) * CIP + 2 * hcp) << 1),
                  quant2(f0, f1, sinvsh[hcp], ok));
        }
    }
    __syncthreads();

    bool flip = false;

    while (true) {
        const unsigned qc = flip ? q1a : q0a;
        const unsigned qn = flip ? q0a : q1a;

        const int nxt = tile + NCTA;
        const bool hasnext = (nxt < NTILES);
        int nb = 0, nby = 0, nbx = 0;
        if (hasnext) {
            nb  = nxt >> 9;
            nby = ((nxt >> 3) & 63) << 2;
            nbx = (nxt & 7) << 5;
        }
        const float* xbn = x + (size_t)nb * C_CH * HW;

        float rawA[6][2], rawB[6][2], rawH[2];

        // stage-A loads: body rows 0..47 (r = 0..2)
        if (hasnext) {
#pragma unroll
            for (int k = 0; k < 6; ++k) {
                int row = wid + (k << 3);
                int r   = row >> 4;
                int cp  = row & 15;
                int gy  = nby + r - 1;
                float f0 = 0.f, f1 = 0.f;
                if ((unsigned)gy < 256u) {
                    const float* p = xbn + (size_t)(2 * cp) * HW + (gy << 8) + nbx + lane;
                    f0 = __ldg(p); f1 = __ldg(p + HW);
                }
                rawA[k][0] = f0; rawA[k][1] = f1;
            }
        }

        // MMA stage s = 0
#pragma unroll
        for (int tap = 0; tap < 9; ++tap) {
            const int dy = tap / 3, dx = tap % 3;
            const unsigned abase = qc +
                ((((wr + dy) * QPX + wx + dx + pxl0) * CIP + cih) << 1);
            const unsigned bbase = wba +
                ((((tap * 32 + b_row) * WCIP) + b_cih) << 1);
            unsigned bf[4][2];
#pragma unroll
            for (int nt = 0; nt < 4; ++nt)
                ldsm_x2(bf[nt][0], bf[nt][1], bbase + ((nt * 8 * WCIP) << 1));
            unsigned a0, a1, a2, a3;
            ldsm_x4(a0, a1, a2, a3, abase);
#pragma unroll
            for (int nt = 0; nt < 4; ++nt)
                mma16816(acc[nt][0], acc[nt][1], acc[nt][2], acc[nt][3],
                         a0, a1, a2, a3, bf[nt][0], bf[nt][1]);
        }

        if (hasnext) {
            // STS stage-A
#pragma unroll
            for (int k = 0; k < 6; ++k) {
                int row = wid + (k << 3);
                int r   = row >> 4;
                int cp  = row & 15;
                bool ok = (unsigned)(nby + r - 1) < 256u;
                sts32(qn + (((r * QPX + lane + 1) * CIP + 2 * cp) << 1),
                      quant2(rawA[k][0], rawA[k][1], sinvsh[cp], ok));
            }
            // stage-B loads: body rows 48..95 (r = 3..5) + halo
#pragma unroll
            for (int k = 6; k < 12; ++k) {
                int row = wid + (k << 3);
                int r   = row >> 4;
                int cp  = row & 15;
                int gy  = nby + r - 1;
                float f0 = 0.f, f1 = 0.f;
                if ((unsigned)gy < 256u) {
                    const float* p = xbn + (size_t)(2 * cp) * HW + (gy << 8) + nbx + lane;
                    f0 = __ldg(p); f1 = __ldg(p + HW);
                }
                rawB[k - 6][0] = f0; rawB[k - 6][1] = f1;
            }
            rawH[0] = 0.f; rawH[1] = 0.f;
            if (tid < 192) {
                int gy = nby + hr - 1;
                int gx = nbx + hpx - 1;
                if (((unsigned)gy < 256u) & ((unsigned)gx < 256u)) {
                    const float* p = xbn + (size_t)(2 * hcp) * HW + (gy << 8) + gx;
                    rawH[0] = __ldg(p); rawH[1] = __ldg(p + HW);
                }
            }
        }

        // MMA stage s = 1
#pragma unroll
        for (int tap = 0; tap < 9; ++tap) {
            const int dy = tap / 3, dx = tap % 3;
            const unsigned abase = qc +
                ((((wr + dy) * QPX + wx + dx + pxl0) * CIP + cih + 16) << 1);
            const unsigned bbase = wba +
                ((((tap * 32 + b_row) * WCIP) + b_cih + 16) << 1);
            unsigned bf[4][2];
#pragma unroll
            for (int nt = 0; nt < 4; ++nt)
                ldsm_x2(bf[nt][0], bf[nt][1], bbase + ((nt * 8 * WCIP) << 1));
            unsigned a0, a1, a2, a3;
            ldsm_x4(a0, a1, a2, a3, abase);
#pragma unroll
            for (int nt = 0; nt < 4; ++nt)
                mma16816(acc[nt][0], acc[nt][1], acc[nt][2], acc[nt][3],
                         a0, a1, a2, a3, bf[nt][0], bf[nt][1]);
        }

        if (hasnext) {
            // STS stage-B + halo
#pragma unroll
            for (int k = 6; k < 12; ++k) {
                int row = wid + (k << 3);
                int r   = row >> 4;
                int cp  = row & 15;
                bool ok = (unsigned)(nby + r - 1) < 256u;
                sts32(qn + (((r * QPX + lane + 1) * CIP + 2 * cp) << 1),
                      quant2(rawB[k - 6][0], rawB[k - 6][1], sinvsh[cp], ok));
            }
            if (tid < 192) {
                bool ok = ((unsigned)(nby + hr - 1) < 256u) &
                          ((unsigned)(nbx + hpx - 1) < 256u);
                sts32(qn + (((hr * QPX + hpx) * CIP + 2 * hcp) << 1),
                      quant2(rawH[0], rawH[1], sinvsh[hcp], ok));
            }
        }

        // ---- epilogue: bias + ReLU + store ----
        {
            float* ob = out + (size_t)b * C_CH * HW;
            const int oy = by + wr;
            const int px = bx + wx + m0;
#pragma unroll
            for (int nt = 0; nt < 4; ++nt) {
                const int co = nt * 8 + cb;
                const float b0 = sbias[co];
                const float b1 = sbias[co + 1];
                float* o0 = ob + (size_t)co * HW + (oy << 8);
                float* o1 = o0 + HW;
                o0[px]     = fmaxf(acc[nt][0] + b0, 0.0f);
                o1[px]     = fmaxf(acc[nt][1] + b1, 0.0f);
                o0[px + 8] = fmaxf(acc[nt][2] + b0, 0.0f);
                o1[px + 8] = fmaxf(acc[nt][3] + b1, 0.0f);
                acc[nt][0] = 0.f; acc[nt][1] = 0.f;
                acc[nt][2] = 0.f; acc[nt][3] = 0.f;
            }
        }

        __syncthreads();
        if (!hasnext) break;
        tile = nxt; b = nb; by = nby; bx = nbx;
        flip = !flip;
    }
}

extern "C" void kernel_launch(void* const* d_in, const int* in_sizes, int n_in,
                              void* d_out, int out_size)
{
    const float* x     = (const float*)d_in[0];
    const float* gamma = (const float*)d_in[1];
    const float* beta  = (const float*)d_in[2];
    const float* mean  = (const float*)d_in[3];
    const float* var   = (const float*)d_in[4];
    const float* w     = (const float*)d_in[5];
    const float* bias  = (const float*)d_in[6];
    float* out = (float*)d_out;

    size_t smem = (size_t)(2 * QTILE + WSZ) * sizeof(__half)
                + 16 * sizeof(float4) + 32 * sizeof(float);
    cudaFuncSetAttribute(tbconv_occ_kernel,
                         cudaFuncAttributeMaxDynamicSharedMemorySize, (int)smem);

    tbconv_occ_kernel<<<NCTA, NT, smem>>>(x, gamma, beta, mean, var, w, bias, out);
}

// round 5
// speedup vs baseline: 4.5974x; 1.0508x over previous
#include <cuda_runtime.h>
#include <cuda_fp16.h>

// ---------------------------------------------------------------------------
// Fused BN -> sign(+-1) -> 3x3 conv -> bias -> ReLU, fp16 tensor-core
// implicit GEMM. Persistent CTAs, double-buffered pipeline, 3 CTAs/SM.
// Tile: 8 rows x 32 px x 32 co; warp = 1 row x 32 px x 32 co (WM=32).
// Weights pre-shuffled into per-thread mma B-fragments (LDS.64, no ldmatrix).
// ---------------------------------------------------------------------------

#define HW      65536
#define C_CH    32

#define QROWS   10           // 8 + 2 halo
#define QPX     34           // 32 + 2 halo
#define CIP     40           // ci stride (halfs) -> 80B px stride, ldsm-safe
#define QTILE   (QROWS * QPX * CIP)   // 13600 halfs
#define NWF     (9 * 2 * 4 * 32)      // 2304 uint2 weight frags

#define OFF_Q0  0
#define OFF_Q1  (QTILE * 2)
#define OFF_WF  (QTILE * 4)           // 54400
#define OFF_SC  (OFF_WF + NWF * 8)    // 72832
#define OFF_SB  (OFF_SC + 256)        // 73088
#define SMEM_BYTES (OFF_SB + 128)     // 73216

#define NT      256
#define NCTA    444                   // 3 per SM x 148
#define NTILES  4096                  // 16 b x 32 y x 8 x

__device__ __forceinline__ void ldsm_x4(unsigned &a0, unsigned &a1,
                                        unsigned &a2, unsigned &a3,
                                        unsigned addr) {
    asm volatile("ldmatrix.sync.aligned.m8n8.x4.shared.b16 {%0,%1,%2,%3}, [%4];"
                 : "=r"(a0), "=r"(a1), "=r"(a2), "=r"(a3) : "r"(addr));
}
__device__ __forceinline__ void mma16816(float &c0, float &c1, float &c2, float &c3,
                                         unsigned a0, unsigned a1, unsigned a2, unsigned a3,
                                         unsigned b0, unsigned b1) {
    asm volatile("mma.sync.aligned.m16n8k16.row.col.f32.f16.f16.f32 "
                 "{%0,%1,%2,%3},{%4,%5,%6,%7},{%8,%9},{%0,%1,%2,%3};"
                 : "+f"(c0), "+f"(c1), "+f"(c2), "+f"(c3)
                 : "r"(a0), "r"(a1), "r"(a2), "r"(a3), "r"(b0), "r"(b1));
}
__device__ __forceinline__ unsigned quant2(float f0, float f1, float4 s, bool ok) {
    float v0 = fmaf(f0, s.x, s.y);
    float v1 = fmaf(f1, s.z, s.w);
    unsigned lo = ok ? (v0 > 0.f ? 0x3C00u : 0xBC00u) : 0u;
    unsigned hi = ok ? (v1 > 0.f ? 0x3C00u : 0xBC00u) : 0u;
    return lo | (hi << 16);
}
__device__ __forceinline__ void sts32(unsigned addr, unsigned val) {
    asm volatile("st.shared.b32 [%0], %1;" :: "r"(addr), "r"(val));
}

// MMA over taps [T0,T1], k-stage S, on buffer qc.
template<int T0, int T1, int S>
__device__ __forceinline__ void mma_taps(unsigned qc, const uint2* __restrict__ wfragsm,
                                         int wr, int pxl0, int cih, int lane,
                                         float acc[2][4][4]) {
#pragma unroll
    for (int tap = T0; tap <= T1; ++tap) {
        const int dy = tap / 3, dx = tap % 3;
        uint2 wf[4];
#pragma unroll
        for (int nt = 0; nt < 4; ++nt)
            wf[nt] = wfragsm[((tap * 2 + S) * 4 + nt) * 32 + lane];
#pragma unroll
        for (int mt = 0; mt < 2; ++mt) {
            unsigned a0, a1, a2, a3;
            unsigned addr = qc +
                (((((wr + dy) * QPX) + mt * 16 + dx + pxl0) * CIP + cih + S * 16) << 1);
            ldsm_x4(a0, a1, a2, a3, addr);
#pragma unroll
            for (int nt = 0; nt < 4; ++nt)
                mma16816(acc[mt][nt][0], acc[mt][nt][1], acc[mt][nt][2], acc[mt][nt][3],
                         a0, a1, a2, a3, wf[nt].x, wf[nt].y);
        }
    }
}

__global__ __launch_bounds__(NT, 3)
void tbconv_wm32_kernel(const float* __restrict__ x,
                        const float* __restrict__ gamma,
                        const float* __restrict__ beta,
                        const float* __restrict__ mean,
                        const float* __restrict__ var,
                        const float* __restrict__ w,
                        const float* __restrict__ bias,
                        float* __restrict__ out)
{
    extern __shared__ char smraw[];
    uint2*  wfragsm = (uint2*)(smraw + OFF_WF);
    float4* sinvsh  = (float4*)(smraw + OFF_SC);
    float*  sbias   = (float*)(smraw + OFF_SB);

    const int tid  = threadIdx.x;
    const int lane = tid & 31;
    const int wid  = tid >> 5;      // warp = output row 0..7

    // ---- one-time setup ----
    if (tid < 16) {
        int c0 = 2 * tid;
        float i0 = gamma[c0]     * rsqrtf(var[c0]     + 1e-4f);
        float i1 = gamma[c0 + 1] * rsqrtf(var[c0 + 1] + 1e-4f);
        sinvsh[tid] = make_float4(i0, beta[c0]     - mean[c0]     * i0,
                                  i1, beta[c0 + 1] - mean[c0 + 1] * i1);
    }
    if (tid < 32) sbias[tid] = bias[tid];
    // weights pre-shuffled into mma B-fragment order:
    // wfrag[((tap*2+s)*4+nt)*32 + t] = {w2(ci,ci+1), w2(ci+8,ci+9)} for
    // co = nt*8 + t/4, ci = s*16 + (t%4)*2   (w is OIHW [co][ci][tap])
    for (int i = tid; i < NWF; i += NT) {
        int t = i & 31, nt = (i >> 5) & 3, s = (i >> 7) & 1, tap = i >> 8;
        int co = nt * 8 + (t >> 2);
        int ci = s * 16 + (t & 3) * 2;
        const float* wb = w + (co * 32 + ci) * 9 + tap;
        __half2 lo = __floats2half2_rn(wb[0],  wb[9]);    // ci, ci+1
        __half2 hi = __floats2half2_rn(wb[72], wb[81]);   // ci+8, ci+9
        uint2 v;
        v.x = *(unsigned*)&lo;
        v.y = *(unsigned*)&hi;
        wfragsm[i] = v;
    }

    const unsigned q0a = (unsigned)__cvta_generic_to_shared(smraw) + OFF_Q0;
    const unsigned q1a = q0a + QTILE * 2;

    const int wr   = wid;                        // output row within tile
    const int pxl0 = (lane & 7) + ((lane >> 3) & 1) * 8;
    const int cih  = (lane >> 4) * 8;
    const int m0   = lane >> 2;
    const int cb   = (lane & 3) * 2;

    // halo decode: set A = all 256 threads (rows 0..7), set B = tid<64 (rows 8..9)
    const int hside = tid & 1;
    const int hcp   = (tid >> 1) & 15;
    const int hr    = tid >> 5;          // 0..7
    const int h2r   = 8 + (tid >> 5);    // 8..9 (tid < 64)
    const int hpx   = hside ? 33 : 0;

    __syncthreads();   // sbias/sinvsh/wfrag visible

    float bias0[4], bias1[4];
#pragma unroll
    for (int nt = 0; nt < 4; ++nt) {
        bias0[nt] = sbias[nt * 8 + cb];
        bias1[nt] = sbias[nt * 8 + cb + 1];
    }

    float acc[2][4][4];
#pragma unroll
    for (int mt = 0; mt < 2; ++mt)
#pragma unroll
        for (int nt = 0; nt < 4; ++nt)
#pragma unroll
            for (int k = 0; k < 4; ++k) acc[mt][nt][k] = 0.0f;

    int tile = blockIdx.x;
    int b  = tile >> 8;
    int by = ((tile >> 3) & 31) << 3;
    int bx = (tile & 7) << 5;

    // ---- prologue: build first tile into q0 ----
    {
        const float* xb = x + (size_t)b * C_CH * HW;
#pragma unroll
        for (int k = 0; k < 20; ++k) {
            int item = wid + (k << 3);       // 0..159
            int r  = item >> 4, cp = item & 15;
            int gy = by + r - 1;
            bool ok = (unsigned)gy < 256u;
            float f0 = 0.f, f1 = 0.f;
            if (ok) {
                const float* p = xb + (size_t)(2 * cp) * HW + (gy << 8) + bx + lane;
                f0 = __ldg(p); f1 = __ldg(p + HW);
            }
            sts32(q0a + (((r * QPX + lane + 1) * CIP + 2 * cp) << 1),
                  quant2(f0, f1, sinvsh[cp], ok));
        }
        {   // halo A
            int gy = by + hr - 1, gx = bx + hpx - 1;
            bool ok = ((unsigned)gy < 256u) & ((unsigned)gx < 256u);
            float f0 = 0.f, f1 = 0.f;
            if (ok) {
                const float* p = xb + (size_t)(2 * hcp) * HW + (gy << 8) + gx;
                f0 = __ldg(p); f1 = __ldg(p + HW);
            }
            sts32(q0a + (((hr * QPX + hpx) * CIP + 2 * hcp) << 1),
                  quant2(f0, f1, sinvsh[hcp], ok));
        }
        if (tid < 64) {   // halo B
            int gy = by + h2r - 1, gx = bx + hpx - 1;
            bool ok = ((unsigned)gy < 256u) & ((unsigned)gx < 256u);
            float f0 = 0.f, f1 = 0.f;
            if (ok) {
                const float* p = xb + (size_t)(2 * hcp) * HW + (gy << 8) + gx;
                f0 = __ldg(p); f1 = __ldg(p + HW);
            }
            sts32(q0a + (((h2r * QPX + hpx) * CIP + 2 * hcp) << 1),
                  quant2(f0, f1, sinvsh[hcp], ok));
        }
    }
    __syncthreads();

    bool flip = false;

#define LOADS(J)                                                              \
    if (hasnext) {                                                            \
        _Pragma("unroll")                                                     \
        for (int k5 = 0; k5 < 5; ++k5) {                                      \
            int item = wid + (((J) * 5 + k5) << 3);                           \
            int r  = item >> 4, cp = item & 15;                               \
            int gy = nby + r - 1;                                             \
            float f0 = 0.f, f1 = 0.f;                                         \
            if ((unsigned)gy < 256u) {                                        \
                const float* p = xbn + (size_t)(2 * cp) * HW + (gy << 8) + nbx + lane; \
                f0 = __ldg(p); f1 = __ldg(p + HW);                            \
            }                                                                 \
            rf[k5][0] = f0; rf[k5][1] = f1;                                   \
        }                                                                     \
    }

#define STS_STAGE(J)                                                          \
    if (hasnext) {                                                            \
        _Pragma("unroll")                                                     \
        for (int k5 = 0; k5 < 5; ++k5) {                                      \
            int item = wid + (((J) * 5 + k5) << 3);                           \
            int r  = item >> 4, cp = item & 15;                               \
            bool ok = (unsigned)(nby + r - 1) < 256u;                         \
            sts32(qn + (((r * QPX + lane + 1) * CIP + 2 * cp) << 1),          \
                  quant2(rf[k5][0], rf[k5][1], sinvsh[cp], ok));              \
        }                                                                     \
    }

    while (true) {
        const unsigned qc = flip ? q1a : q0a;
        const unsigned qn = flip ? q0a : q1a;

        const int nxt = tile + NCTA;
        const bool hasnext = (nxt < NTILES);
        int nb = 0, nby = 0, nbx = 0;
        if (hasnext) {
            nb  = nxt >> 8;
            nby = ((nxt >> 3) & 31) << 3;
            nbx = (nxt & 7) << 5;
        }
        const float* xbn = x + (size_t)nb * C_CH * HW;

        float rf[5][2];
        float hA[2] = {0.f, 0.f}, hB[2] = {0.f, 0.f};

        LOADS(0)
        mma_taps<0, 4, 0>(qc, wfragsm, wr, pxl0, cih, lane, acc);
        STS_STAGE(0)
        LOADS(1)
        mma_taps<5, 8, 0>(qc, wfragsm, wr, pxl0, cih, lane, acc);
        STS_STAGE(1)
        LOADS(2)
        mma_taps<0, 4, 1>(qc, wfragsm, wr, pxl0, cih, lane, acc);
        STS_STAGE(2)
        LOADS(3)
        if (hasnext) {
            int gy = nby + hr - 1, gx = nbx + hpx - 1;
            if (((unsigned)gy < 256u) & ((unsigned)gx < 256u)) {
                const float* p = xbn + (size_t)(2 * hcp) * HW + (gy << 8) + gx;
                hA[0] = __ldg(p); hA[1] = __ldg(p + HW);
            }
            if (tid < 64) {
                int gy2 = nby + h2r - 1;
                if (((unsigned)gy2 < 256u) & ((unsigned)gx < 256u)) {
                    const float* p = xbn + (size_t)(2 * hcp) * HW + (gy2 << 8) + gx;
                    hB[0] = __ldg(p); hB[1] = __ldg(p + HW);
                }
            }
        }
        mma_taps<5, 8, 1>(qc, wfragsm, wr, pxl0, cih, lane, acc);
        STS_STAGE(3)
        if (hasnext) {
            bool okA = ((unsigned)(nby + hr - 1) < 256u) &
                       ((unsigned)(nbx + hpx - 1) < 256u);
            sts32(qn + (((hr * QPX + hpx) * CIP + 2 * hcp) << 1),
                  quant2(hA[0], hA[1], sinvsh[hcp], okA));
            if (tid < 64) {
                bool okB = ((unsigned)(nby + h2r - 1) < 256u) &
                           ((unsigned)(nbx + hpx - 1) < 256u);
                sts32(qn + (((h2r * QPX + hpx) * CIP + 2 * hcp) << 1),
                      quant2(hB[0], hB[1], sinvsh[hcp], okB));
            }
        }

        // ---- epilogue ----
        {
            float* ob = out + (size_t)b * C_CH * HW;
            const int oy = by + wr;
#pragma unroll
            for (int nt = 0; nt < 4; ++nt) {
                const int co = nt * 8 + cb;
                float* o0 = ob + (size_t)co * HW + (oy << 8);
                float* o1 = o0 + HW;
#pragma unroll
                for (int mt = 0; mt < 2; ++mt) {
                    const int px = bx + mt * 16 + m0;
                    o0[px]     = fmaxf(acc[mt][nt][0] + bias0[nt], 0.0f);
                    o1[px]     = fmaxf(acc[mt][nt][1] + bias1[nt], 0.0f);
                    o0[px + 8] = fmaxf(acc[mt][nt][2] + bias0[nt], 0.0f);
                    o1[px + 8] = fmaxf(acc[mt][nt][3] + bias1[nt], 0.0f);
                    acc[mt][nt][0] = 0.f; acc[mt][nt][1] = 0.f;
                    acc[mt][nt][2] = 0.f; acc[mt][nt][3] = 0.f;
                }
            }
        }

        __syncthreads();
        if (!hasnext) break;
        tile = nxt; b = nb; by = nby; bx = nbx;
        flip = !flip;
    }
#undef LOADS
#undef STS_STAGE
}

extern "C" void kernel_launch(void* const* d_in, const int* in_sizes, int n_in,
                              void* d_out, int out_size)
{
    const float* x     = (const float*)d_in[0];
    const float* gamma = (const float*)d_in[1];
    const float* beta  = (const float*)d_in[2];
    const float* mean  = (const float*)d_in[3];
    const float* var   = (const float*)d_in[4];
    const float* w     = (const float*)d_in[5];
    const float* bias  = (const float*)d_in[6];
    float* out = (float*)d_out;

    cudaFuncSetAttribute(tbconv_wm32_kernel,
                         cudaFuncAttributeMaxDynamicSharedMemorySize, SMEM_BYTES);

    tbconv_wm32_kernel<<<NCTA, NT, SMEM_BYTES>>>(x, gamma, beta, mean, var, w, bias, out);
}